// round 9
// baseline (speedup 1.0000x reference)
#include <cuda_runtime.h>
#include <cuda_bf16.h>

#define THREADS 256
#define WIN     9
#define EDGE    4
#define B_MAX   131072
#define T_BINS  2048
#define TILES   64

__device__ int g_idx[B_MAX];
__device__ int g_perm[B_MAX];
__device__ int g_tilehist[T_BINS * TILES];  // [bin][tile] counts -> in-bin tile offsets
__device__ int g_bintot[T_BINS];
__device__ int g_binbase[T_BINS];

// ---------- nearest-anchor index: analytic + exact fp32 argmin verify ----------
__device__ __forceinline__ int nearest_idx(float xv, const float* __restrict__ etab, int T)
{
    const float e0 = __ldg(&etab[0]);
    const float eN = __ldg(&etab[T - 1]);
    const float step = (eN - e0) / (float)(T - 1);
    int i0 = (int)floorf((xv - e0) / step);
    int idx = 0;
    float best = 3.4e38f;
    #pragma unroll
    for (int k = 0; k < 4; k++) {
        int cc = min(max(i0 - 1 + k, 0), T - 1);
        float d = xv - __ldg(&etab[cc]);
        d *= d;
        if (d < best) { best = d; idx = cc; }   // strict '<' == argmin first-occurrence
    }
    return idx;
}

// ---------- pass 1: per-tile histogram (smem atomics only) + g_idx ----------
__global__ __launch_bounds__(1024)
void k_hist(const float* __restrict__ x, const float* __restrict__ etab,
            int B, int T, int tileQ)
{
    __shared__ int cnt_s[T_BINS];
    const int t = blockIdx.x;
    for (int i = threadIdx.x; i < T_BINS; i += blockDim.x) cnt_s[i] = 0;
    __syncthreads();

    const int q0 = t * tileQ;
    for (int i = threadIdx.x; i < tileQ; i += blockDim.x) {
        int q = q0 + i;
        if (q < B) {
            int idx = nearest_idx(x[q], etab, T);
            g_idx[q] = idx;
            atomicAdd(&cnt_s[idx], 1);
        }
    }
    __syncthreads();
    for (int i = threadIdx.x; i < T_BINS; i += blockDim.x)
        g_tilehist[i * TILES + t] = cnt_s[i];
}

// ---------- pass 2: per-bin exclusive scan over tiles (thread per bin) ----------
__global__ __launch_bounds__(1024)
void k_binsum()
{
    int b = blockIdx.x * blockDim.x + threadIdx.x;
    if (b >= T_BINS) return;
    int s = 0;
    #pragma unroll 8
    for (int t = 0; t < TILES; t++) {
        int c = g_tilehist[b * TILES + t];
        g_tilehist[b * TILES + t] = s;
        s += c;
    }
    g_bintot[b] = s;
}

// ---------- pass 3: exclusive scan over 2048 bin totals (one block) ----------
__global__ __launch_bounds__(1024)
void k_binscan()
{
    __shared__ int s[1024];
    int i = threadIdx.x;
    int a = g_bintot[2 * i];
    int b = g_bintot[2 * i + 1];
    s[i] = a + b;
    #pragma unroll
    for (int off = 1; off < 1024; off <<= 1) {
        __syncthreads();
        int v = (i >= off) ? s[i - off] : 0;
        __syncthreads();
        s[i] += v;
    }
    __syncthreads();
    int excl_pair = s[i] - (a + b);
    g_binbase[2 * i]     = excl_pair;
    g_binbase[2 * i + 1] = excl_pair + a;
}

// ---------- pass 4: contention-free scatter (smem local rank only) ----------
__global__ __launch_bounds__(1024)
void k_scatter2(int B, int tileQ)
{
    __shared__ int rank_s[T_BINS];
    const int t = blockIdx.x;
    for (int i = threadIdx.x; i < T_BINS; i += blockDim.x) rank_s[i] = 0;
    __syncthreads();

    const int q0 = t * tileQ;
    for (int i = threadIdx.x; i < tileQ; i += blockDim.x) {
        int q = q0 + i;
        if (q < B) {
            int idx = g_idx[q];
            int lr  = atomicAdd(&rank_s[idx], 1);
            int pos = g_binbase[idx] + g_tilehist[idx * TILES + t] + lr;
            g_perm[pos] = q;
        }
    }
}

// ---------- pass 5: block-per-bin main kernel ----------
__global__ __launch_bounds__(THREADS, 8)
void k_main(const float* __restrict__ x,
            const float* __restrict__ etab,
            const float* __restrict__ tctab,
            const float* __restrict__ vtab,
            float* __restrict__ out,
            int B, int T)
{
    const int bin   = blockIdx.x;
    const int cnt   = g_bintot[bin];
    if (cnt == 0) return;
    const int start = g_binbase[bin];

    const int warp = threadIdx.x >> 5;
    const int lane = threadIdx.x & 31;
    const int nwarp = THREADS / 32;

    // whole block shares idx == bin
    const float tc = __ldg(&tctab[bin]);            // UNCLIPPED idx (matches reference)
    const int idx_c = min(max(bin, EDGE), T - 1 - EDGE);
    const int base = idx_c - EDGE;

    const float4* vt = (const float4*)vtab;         // rows of 16 float4
    const int q   = lane >> 3;                      // 0..3
    const int sub = lane & 7;                       // 0..7

    for (int it = warp * 4; it < cnt; it += nwarp * 4) {
        // Phase 1 (lanes 0..3): softmax for up to 4 queries of this chunk
        float wv[WIN];
        int gq = -1;
        if (lane < 4) {
            int p = it + lane;
            if (p < cnt) {
                gq = g_perm[start + p];
                const float xv = x[gq];
                float m = -3.4e38f;
                #pragma unroll
                for (int j = 0; j < WIN; j++) {
                    float e = __ldg(&etab[base + j]);
                    float d = xv - e;
                    float l = -(d * d) * tc;
                    wv[j] = l;
                    m = fmaxf(m, l);
                }
                float sum = 0.0f;
                #pragma unroll
                for (int j = 0; j < WIN; j++) {
                    float pp = __expf(wv[j] - m);
                    wv[j] = pp;
                    sum += pp;
                }
                const float inv = __frcp_rn(sum);
                #pragma unroll
                for (int j = 0; j < WIN; j++) wv[j] *= inv;
            }
        }

        // broadcast to the 8 lanes serving each query
        gq = __shfl_sync(0xffffffffu, gq, q);
        #pragma unroll
        for (int j = 0; j < WIN; j++) wv[j] = __shfl_sync(0xffffffffu, wv[j], q);

        if (gq >= 0) {
            float4 a0 = make_float4(0.f, 0.f, 0.f, 0.f);
            float4 a1 = make_float4(0.f, 0.f, 0.f, 0.f);
            #pragma unroll
            for (int j = 0; j < WIN; j++) {
                const float4* row = vt + (size_t)(base + j) * 16;
                float4 v0 = __ldg(row + sub);       // same line for all 4 query-groups
                float4 v1 = __ldg(row + 8 + sub);
                float wj = wv[j];
                a0.x = fmaf(wj, v0.x, a0.x);
                a0.y = fmaf(wj, v0.y, a0.y);
                a0.z = fmaf(wj, v0.z, a0.z);
                a0.w = fmaf(wj, v0.w, a0.w);
                a1.x = fmaf(wj, v1.x, a1.x);
                a1.y = fmaf(wj, v1.y, a1.y);
                a1.z = fmaf(wj, v1.z, a1.z);
                a1.w = fmaf(wj, v1.w, a1.w);
            }
            float4* o = (float4*)(out + (size_t)gq * 64);
            __stcs(o + sub,     a0);
            __stcs(o + 8 + sub, a1);
        }
    }
}

extern "C" void kernel_launch(void* const* d_in, const int* in_sizes, int n_in,
                              void* d_out, int out_size)
{
    const float* x     = (const float*)d_in[0];   // [B,1]
    const float* etab  = (const float*)d_in[1];   // [T,1]
    const float* tctab = (const float*)d_in[2];   // [T,1]
    const float* vtab  = (const float*)d_in[3];   // [T,D]
    float* out = (float*)d_out;

    const int B = in_sizes[0];                    // 131072
    const int T = in_sizes[1];                    // 2048

    const int tileQ = (B + TILES - 1) / TILES;    // 2048

    k_hist    <<<TILES, 1024>>>(x, etab, B, T, tileQ);
    k_binsum  <<<(T_BINS + 1023) / 1024, 1024>>>();
    k_binscan <<<1, 1024>>>();
    k_scatter2<<<TILES, 1024>>>(B, tileQ);
    k_main    <<<T_BINS, THREADS>>>(x, etab, tctab, vtab, out, B, T);
}

// round 10
// speedup vs baseline: 4.2980x; 4.2980x over previous
#include <cuda_runtime.h>
#include <cuda_bf16.h>

#define THREADS 512
#define NWARP   (THREADS / 32)
#define QBLK    1024
#define WIN     9
#define EDGE    4
#define T_BINS  2048

__device__ __forceinline__ int nearest_idx(float xv, const float* __restrict__ etab,
                                           int T, float e0, float inv_step)
{
    int i0 = (int)floorf((xv - e0) * inv_step);
    int idx = 0;
    float best = 3.4e38f;
    #pragma unroll
    for (int k = 0; k < 4; k++) {
        int cc = min(max(i0 - 1 + k, 0), T - 1);
        float d = xv - __ldg(&etab[cc]);
        d *= d;
        if (d < best) { best = d; idx = cc; }   // strict '<' == argmin first-occurrence
    }
    return idx;
}

__global__ __launch_bounds__(THREADS, 2)
void hwnet_kernel(const float* __restrict__ x,
                  const float* __restrict__ etab,
                  const float* __restrict__ tctab,
                  const float* __restrict__ vtab,
                  float* __restrict__ out,
                  int B, int T)
{
    __shared__ int   s_hist[T_BINS];
    __shared__ int   s_ord[QBLK];      // sorted position -> local query id
    __shared__ int   s_bin[QBLK];      // local query id -> anchor idx
    __shared__ float s_x[QBLK];        // local query id -> x value
    __shared__ int   s_wsum[NWARP];

    const int tid  = threadIdx.x;
    const int lane = tid & 31;
    const int warp = tid >> 5;
    const int q0   = blockIdx.x * QBLK;

    // ---- Phase A: stage x, compute anchor idx, build smem histogram
    for (int i = tid; i < T_BINS; i += THREADS) s_hist[i] = 0;
    __syncthreads();

    {
        const float e0 = __ldg(&etab[0]);
        const float eN = __ldg(&etab[T - 1]);
        const float inv_step = (float)(T - 1) / (eN - e0);
        #pragma unroll
        for (int i = tid; i < QBLK; i += THREADS) {
            int q = q0 + i;
            float xv = (q < B) ? x[q] : 0.0f;
            s_x[i] = xv;
            int idx = nearest_idx(xv, etab, T, e0, inv_step);
            s_bin[i] = idx;
            atomicAdd(&s_hist[idx], 1);
        }
    }
    __syncthreads();

    // ---- Phase B: exclusive scan of 2048-bin histogram (4 bins/thread + warp scans)
    {
        const int b = tid * 4;
        int c0 = s_hist[b], c1 = s_hist[b + 1], c2 = s_hist[b + 2], c3 = s_hist[b + 3];
        int sum = c0 + c1 + c2 + c3;
        int v = sum;
        #pragma unroll
        for (int off = 1; off < 32; off <<= 1) {
            int n = __shfl_up_sync(0xffffffffu, v, off);
            if (lane >= off) v += n;
        }
        if (lane == 31) s_wsum[warp] = v;
        __syncthreads();
        if (warp == 0) {
            int w = (lane < NWARP) ? s_wsum[lane] : 0;
            #pragma unroll
            for (int off = 1; off < NWARP; off <<= 1) {
                int n = __shfl_up_sync(0xffffffffu, w, off);
                if (lane >= off) w += n;
            }
            if (lane < NWARP) s_wsum[lane] = w;
        }
        __syncthreads();
        int wbase = (warp > 0) ? s_wsum[warp - 1] : 0;
        int excl = wbase + v - sum;
        s_hist[b]     = excl;
        s_hist[b + 1] = excl + c0;
        s_hist[b + 2] = excl + c0 + c1;
        s_hist[b + 3] = excl + c0 + c1 + c2;
    }
    __syncthreads();

    // ---- Phase C: scatter local ids into bin-sorted order (smem cursor)
    #pragma unroll
    for (int i = tid; i < QBLK; i += THREADS) {
        int pos = atomicAdd(&s_hist[s_bin[i]], 1);
        s_ord[pos] = i;
    }
    __syncthreads();

    // ---- Phase D: consume in sorted order (R3 consumer; adjacent queries share lines)
    const int qsel = lane >> 3;          // 0..3: which of the warp's 4 queries
    const int sub  = lane & 7;           // 0..7: which 16B chunk of D=64
    const float4* vt = (const float4*)vtab;

    for (int it = warp * 4; it < QBLK; it += NWARP * 4) {
        float wv[WIN];
        int qid = 0, bb = 0;
        if (lane < 4) {
            qid = s_ord[it + lane];
            const float xv = s_x[qid];
            const int idx = s_bin[qid];
            const float tc = __ldg(&tctab[idx]);          // UNCLIPPED idx (matches ref)
            const int idx_c = min(max(idx, EDGE), T - 1 - EDGE);
            bb = idx_c - EDGE;

            float m = -3.4e38f;
            #pragma unroll
            for (int j = 0; j < WIN; j++) {
                float e = __ldg(&etab[bb + j]);
                float d = xv - e;
                float l = -(d * d) * tc;
                wv[j] = l;
                m = fmaxf(m, l);
            }
            float sum = 0.0f;
            #pragma unroll
            for (int j = 0; j < WIN; j++) {
                float p = __expf(wv[j] - m);
                wv[j] = p;
                sum += p;
            }
            const float inv = __frcp_rn(sum);
            #pragma unroll
            for (int j = 0; j < WIN; j++) wv[j] *= inv;
        }

        // broadcast to the 8 lanes serving each query
        bb  = __shfl_sync(0xffffffffu, bb,  qsel);
        qid = __shfl_sync(0xffffffffu, qid, qsel);
        #pragma unroll
        for (int j = 0; j < WIN; j++) wv[j] = __shfl_sync(0xffffffffu, wv[j], qsel);

        const int gq = q0 + qid;
        if (gq < B) {
            float4 a0 = make_float4(0.f, 0.f, 0.f, 0.f);
            float4 a1 = make_float4(0.f, 0.f, 0.f, 0.f);
            #pragma unroll
            for (int j = 0; j < WIN; j++) {
                const float4* row = vt + (size_t)(bb + j) * 16;
                float4 v0 = __ldg(row + sub);
                float4 v1 = __ldg(row + 8 + sub);
                float wj = wv[j];
                a0.x = fmaf(wj, v0.x, a0.x);
                a0.y = fmaf(wj, v0.y, a0.y);
                a0.z = fmaf(wj, v0.z, a0.z);
                a0.w = fmaf(wj, v0.w, a0.w);
                a1.x = fmaf(wj, v1.x, a1.x);
                a1.y = fmaf(wj, v1.y, a1.y);
                a1.z = fmaf(wj, v1.z, a1.z);
                a1.w = fmaf(wj, v1.w, a1.w);
            }
            float4* o = (float4*)(out + (size_t)gq * 64);
            __stcs(o + sub,     a0);
            __stcs(o + 8 + sub, a1);
        }
    }
}

extern "C" void kernel_launch(void* const* d_in, const int* in_sizes, int n_in,
                              void* d_out, int out_size)
{
    const float* x     = (const float*)d_in[0];   // [B,1]
    const float* etab  = (const float*)d_in[1];   // [T,1]
    const float* tctab = (const float*)d_in[2];   // [T,1]
    const float* vtab  = (const float*)d_in[3];   // [T,D]
    float* out = (float*)d_out;

    const int B = in_sizes[0];                    // 131072
    const int T = in_sizes[1];                    // 2048

    const int blocks = (B + QBLK - 1) / QBLK;     // 128
    hwnet_kernel<<<blocks, THREADS>>>(x, etab, tctab, vtab, out, B, T);
}